// round 6
// baseline (speedup 1.0000x reference)
#include <cuda_runtime.h>

// Unfold (im2col) for x:(B=16, C=128, H=64, W=64), k=3, pad=1.
// out[b, c*9 + p, h*W + w] = x[b, c, h+dh-1, w+dw-1] (zero-padded), p = dh*3+dw.
// DRAM-write bound: 302 MB write; input is L2-resident across graph replays.
//
// R5: 8 outputs/thread, ALL loads front-batched (max MLP), 18 plain STG.128
// in one burst. No .cs hints (R2's regression traced to evict-first causing
// partial-line L2 writebacks).

#define B_ 16
#define C_ 128
#define H_ 64
#define W_ 64
#define PLANE (H_ * W_)   // 4096

__global__ __launch_bounds__(128) void unfold_kernel(
    const float* __restrict__ x, float* __restrict__ out)
{
    int idx = blockIdx.x * blockDim.x + threadIdx.x;
    // Each thread handles 8 consecutive w of one (b, c, h) row.
    // idx layout: [bc (11b)] [h (6b)] [wg (3b)]
    int wg = idx & 7;            // w-group 0..7
    int h  = (idx >> 3) & 63;    // 0..63
    int bc = idx >> 9;           // b*C + c, 0..2047
    int w0 = wg << 3;            // 0,8,...,56

    const float* plane = x + (size_t)bc * PLANE;

    // Halo window: rows h-1..h+1, cols w0-1..w0+8 (10 values per row).
    // All loads issued up front: per row = scalar + 2x float4 + scalar.
    float v[3][10];
#pragma unroll
    for (int r = 0; r < 3; r++) {
        int hh = h + r - 1;
        if (hh >= 0 && hh < H_) {
            const float* row = plane + hh * W_;
            v[r][0] = (w0 > 0) ? row[w0 - 1] : 0.0f;
            float4 a = *reinterpret_cast<const float4*>(row + w0);
            float4 b = *reinterpret_cast<const float4*>(row + w0 + 4);
            v[r][1] = a.x; v[r][2] = a.y; v[r][3] = a.z; v[r][4] = a.w;
            v[r][5] = b.x; v[r][6] = b.y; v[r][7] = b.z; v[r][8] = b.w;
            v[r][9] = (w0 < W_ - 8) ? row[w0 + 8] : 0.0f;
        } else {
#pragma unroll
            for (int c = 0; c < 10; c++) v[r][c] = 0.0f;
        }
    }

    // 18 coalesced plain STG.128 (2 per kernel position), one burst.
    float* outp = out + (size_t)bc * 9 * PLANE + h * W_ + w0;
#pragma unroll
    for (int p = 0; p < 9; p++) {
        int r  = p / 3;
        int cc = p % 3;
        float4 o0 = make_float4(v[r][cc],     v[r][cc + 1], v[r][cc + 2], v[r][cc + 3]);
        float4 o1 = make_float4(v[r][cc + 4], v[r][cc + 5], v[r][cc + 6], v[r][cc + 7]);
        *reinterpret_cast<float4*>(outp + (size_t)p * PLANE)     = o0;
        *reinterpret_cast<float4*>(outp + (size_t)p * PLANE + 4) = o1;
    }
}

extern "C" void kernel_launch(void* const* d_in, const int* in_sizes, int n_in,
                              void* d_out, int out_size)
{
    const float* x = (const float*)d_in[0];
    // d_in[1] is the identity "weights" buffer — unused (eye(9) by construction).
    float* out = (float*)d_out;

    const int total  = B_ * C_ * H_ * (W_ / 8);  // 1,048,576 threads
    const int tpb    = 128;
    const int blocks = total / tpb;              // 8192
    unfold_kernel<<<blocks, tpb>>>(x, out);
}

// round 7
// speedup vs baseline: 1.3990x; 1.3990x over previous
#include <cuda_runtime.h>

// Unfold (im2col) for x:(B=16, C=128, H=64, W=64), k=3, pad=1.
// out[b, c*9 + p, h*W + w] = x[b, c, h+dh-1, w+dw-1] (zero-padded), p = dh*3+dw.
// DRAM-write bound: 302 MB write + ~34 MB read.
//
// R6: R3 shape (4 outputs/thread, fully coalesced STG.128) with edge halo
// values obtained via warp shuffle instead of scalar loads. Per thread:
// 3x LDG.128 (front-batched), 6 shuffles, 9x STG.128.
// Lanes where the shuffle crosses an h-row (wg==0 / wg==15) are exactly the
// zero-pad lanes, so the boundary predicates mask the cross-row garbage.

#define B_ 16
#define C_ 128
#define H_ 64
#define W_ 64
#define PLANE (H_ * W_)   // 4096

__global__ __launch_bounds__(256) void unfold_kernel(
    const float* __restrict__ x, float* __restrict__ out)
{
    int idx = blockIdx.x * blockDim.x + threadIdx.x;
    // Each thread handles 4 consecutive w of one (b, c, h) row.
    // idx layout: [bc (11b)] [h (6b)] [wg (4b)]
    int wg = idx & 15;           // w-group 0..15 (lane & 15)
    int h  = (idx >> 4) & 63;    // 0..63
    int bc = idx >> 10;          // b*C + c, 0..2047
    int w0 = wg << 2;            // 0,4,...,60

    const float* plane = x + (size_t)bc * PLANE;

    // Front-batch the 3 aligned float4 loads (rows h-1, h, h+1).
    float4 a[3];
#pragma unroll
    for (int r = 0; r < 3; r++) {
        int hh = h + r - 1;
        if (hh >= 0 && hh < H_) {
            a[r] = *reinterpret_cast<const float4*>(plane + hh * W_ + w0);
        } else {
            a[r] = make_float4(0.f, 0.f, 0.f, 0.f);
        }
    }

    // Edge halo values from neighbor lanes. Within a half-warp all lanes share
    // the same h (wg is the low 4 bits), so shuffles stay in-row except at
    // wg==0 / wg==15 which are the zero-pad lanes anyway.
    float v0[3], v5[3];
#pragma unroll
    for (int r = 0; r < 3; r++) {
        float left  = __shfl_up_sync(0xffffffffu, a[r].w, 1);
        float right = __shfl_down_sync(0xffffffffu, a[r].x, 1);
        v0[r] = (wg == 0)  ? 0.0f : left;
        v5[r] = (wg == 15) ? 0.0f : right;
    }

    // 9 fully coalesced STG.128 (warp footprint: 512B contiguous each).
    float* outp = out + (size_t)bc * 9 * PLANE + h * W_ + w0;
#pragma unroll
    for (int r = 0; r < 3; r++) {
        float* op = outp + (size_t)(r * 3) * PLANE;
        *reinterpret_cast<float4*>(op)             = make_float4(v0[r],  a[r].x, a[r].y, a[r].z);
        *reinterpret_cast<float4*>(op + PLANE)     = a[r];
        *reinterpret_cast<float4*>(op + 2 * PLANE) = make_float4(a[r].y, a[r].z, a[r].w, v5[r]);
    }
}

extern "C" void kernel_launch(void* const* d_in, const int* in_sizes, int n_in,
                              void* d_out, int out_size)
{
    const float* x = (const float*)d_in[0];
    // d_in[1] is the identity "weights" buffer — unused (eye(9) by construction).
    float* out = (float*)d_out;

    const int total  = B_ * C_ * H_ * (W_ / 4);  // 2,097,152 threads
    const int tpb    = 256;
    const int blocks = total / tpb;              // 8192
    unfold_kernel<<<blocks, tpb>>>(x, out);
}

// round 8
// speedup vs baseline: 1.4230x; 1.0172x over previous
#include <cuda_runtime.h>

// Unfold (im2col) for x:(B=16, C=128, H=64, W=64), k=3, pad=1.
// out[b, c*9 + p, h*W + w] = x[b, c, h+dh-1, w+dw-1] (zero-padded), p = dh*3+dw.
// DRAM-write bound: 302 MB write; measured write ceiling ~5.5 TB/s.
//
// R7: h-pair per thread. 4 aligned LDG.128 (rows h-1..h+2) serve the 6
// row-outputs of rows h and h+1 (18 STG.128). Edge halo values via warp
// shuffle (wg == lane&15, so shuffles stay in-row except at the zero-pad
// lanes). Coalescing: every STG warp-instruction covers 512B contiguous.

#define B_ 16
#define C_ 128
#define H_ 64
#define W_ 64
#define PLANE (H_ * W_)   // 4096

__global__ __launch_bounds__(256) void unfold_kernel(
    const float* __restrict__ x, float* __restrict__ out)
{
    int idx = blockIdx.x * blockDim.x + threadIdx.x;
    // Each thread handles 4 consecutive w of TWO (b, c, h) rows: h=2*hp, 2*hp+1.
    // idx layout: [bc (11b)] [hp (5b)] [wg (4b)]
    int wg = idx & 15;           // w-group 0..15 (== lane & 15)
    int hp = (idx >> 4) & 31;    // h-pair 0..31
    int bc = idx >> 9;           // b*C + c, 0..2047
    int w0 = wg << 2;            // 0,4,...,60
    int h0 = hp << 1;            // 0,2,...,62

    const float* plane = x + (size_t)bc * PLANE;

    // Front-batch 4 aligned float4 loads: rows h0-1, h0, h0+1, h0+2.
    float4 a[4];
#pragma unroll
    for (int r = 0; r < 4; r++) {
        int hh = h0 + r - 1;
        if (hh >= 0 && hh < H_) {
            a[r] = *reinterpret_cast<const float4*>(plane + hh * W_ + w0);
        } else {
            a[r] = make_float4(0.f, 0.f, 0.f, 0.f);
        }
    }

    // Edge halo values from neighbor lanes (in-row; pad lanes masked).
    float e0[4], e5[4];
#pragma unroll
    for (int r = 0; r < 4; r++) {
        float left  = __shfl_up_sync(0xffffffffu, a[r].w, 1);
        float right = __shfl_down_sync(0xffffffffu, a[r].x, 1);
        e0[r] = (wg == 0)  ? 0.0f : left;
        e5[r] = (wg == 15) ? 0.0f : right;
    }

    // 18 fully coalesced STG.128: for output rows h0 (uses a[0..2]) and
    // h0+1 (uses a[1..3]), positions p = r*3 + {0,1,2}.
    float* outp = out + (size_t)bc * 9 * PLANE + h0 * W_ + w0;
#pragma unroll
    for (int hr = 0; hr < 2; hr++) {            // output row h0+hr
        float* obase = outp + hr * W_;
#pragma unroll
        for (int r = 0; r < 3; r++) {           // kernel row
            int s = hr + r;                     // source row index into a[]
            float* op = obase + (size_t)(r * 3) * PLANE;
            *reinterpret_cast<float4*>(op)             = make_float4(e0[s],  a[s].x, a[s].y, a[s].z);
            *reinterpret_cast<float4*>(op + PLANE)     = a[s];
            *reinterpret_cast<float4*>(op + 2 * PLANE) = make_float4(a[s].y, a[s].z, a[s].w, e5[s]);
        }
    }
}

extern "C" void kernel_launch(void* const* d_in, const int* in_sizes, int n_in,
                              void* d_out, int out_size)
{
    const float* x = (const float*)d_in[0];
    // d_in[1] is the identity "weights" buffer — unused (eye(9) by construction).
    float* out = (float*)d_out;

    const int total  = B_ * C_ * (H_ / 2) * (W_ / 4);  // 1,048,576 threads
    const int tpb    = 256;
    const int blocks = total / tpb;                    // 4096
    unfold_kernel<<<blocks, tpb>>>(x, out);
}